// round 4
// baseline (speedup 1.0000x reference)
#include <cuda_runtime.h>

#define BATCH 256
#define CHAN  512
#define SEQL  2048
#define HID   32
#define FLEN  8

// Per-sample loss scratch
__device__ float g_loss[BATCH];

// ---------------------------------------------------------------------------
// Fused kernel: one block (1024 threads = 32 warps) per batch sample.
//  Phase 1: warp w computes stat[b, c] for c in [w*16, w*16+16) via
//           coalesced float4 streaming loads + warp max-reduce.
//  Phase 2: warp w computes h1[w] (warp-cooperative coalesced dot over W1 row).
//  Phase 3: warp 0 computes h2, filters, writes lo/hi, computes per-sample loss.
// ---------------------------------------------------------------------------
__global__ void __launch_bounds__(1024) fused_kernel(
    const float* __restrict__ x,
    const float* __restrict__ W1, const float* __restrict__ b1,
    const float* __restrict__ W2, const float* __restrict__ b2,
    const float* __restrict__ W3, const float* __restrict__ b3,
    float* __restrict__ out)
{
    __shared__ float s_stat[CHAN];
    __shared__ float s_h1[HID];
    __shared__ float s_h2[HID];
    __shared__ float s_f[2 * FLEN];

    const int b    = blockIdx.x;
    const int warp = threadIdx.x >> 5;   // 0..31
    const int lane = threadIdx.x & 31;

    // ---- Phase 1: max over L for 16 rows per warp -------------------------
    // Row (b, c) = x + (b*CHAN + c)*SEQL ; as float4: 512 per row.
    const float4* base = reinterpret_cast<const float4*>(x)
                       + ((size_t)b * CHAN + warp * 16) * (SEQL / 4);
#pragma unroll
    for (int r = 0; r < 16; ++r) {
        const float4* row = base + r * (SEQL / 4);
        float m = -3.402823466e38f;
#pragma unroll
        for (int i = 0; i < 16; ++i) {
            float4 v = __ldcs(row + i * 32 + lane);
            m = fmaxf(m, fmaxf(fmaxf(v.x, v.y), fmaxf(v.z, v.w)));
        }
#pragma unroll
        for (int off = 16; off; off >>= 1)
            m = fmaxf(m, __shfl_xor_sync(0xffffffffu, m, off));
        if (lane == 0) s_stat[warp * 16 + r] = m;
    }
    __syncthreads();

    // ---- Phase 2: h1[warp] = relu(dot(stat, W1[warp,:]) + b1[warp]) -------
    {
        const float4* w4 = reinterpret_cast<const float4*>(W1 + warp * CHAN);
        const float4* s4 = reinterpret_cast<const float4*>(s_stat);
        float p = 0.0f;
#pragma unroll
        for (int i = 0; i < 4; ++i) {
            float4 wv = __ldg(w4 + i * 32 + lane);
            float4 sv = s4[i * 32 + lane];
            p = fmaf(wv.x, sv.x, p);
            p = fmaf(wv.y, sv.y, p);
            p = fmaf(wv.z, sv.z, p);
            p = fmaf(wv.w, sv.w, p);
        }
#pragma unroll
        for (int off = 16; off; off >>= 1)
            p += __shfl_xor_sync(0xffffffffu, p, off);
        if (lane == 0) s_h1[warp] = fmaxf(p + b1[warp], 0.0f);
    }
    __syncthreads();

    // ---- Phase 3: tiny layers + loss, warp 0 only -------------------------
    if (warp == 0) {
        const int t = lane;

        // h2 = relu(h1 @ W2^T + b2): thread t owns unit t
        {
            float acc = b2[t];
            const float* w = W2 + t * HID;
#pragma unroll
            for (int k = 0; k < HID; ++k)
                acc = fmaf(s_h1[k], __ldg(w + k), acc);
            s_h2[t] = fmaxf(acc, 0.0f);
        }
        __syncwarp();

        // filters = h2 @ W3^T + b3 (16 outputs)
        if (t < 2 * FLEN) {
            float acc = b3[t];
            const float* w = W3 + t * HID;
#pragma unroll
            for (int k = 0; k < HID; ++k)
                acc = fmaf(s_h2[k], __ldg(w + k), acc);
            s_f[t] = acc;
        }
        __syncwarp();

        // Outputs: out[0:2048] = lo, out[2048:4096] = hi
        if (t < FLEN) {
            out[b * FLEN + t]                = s_f[t];
            out[BATCH * FLEN + b * FLEN + t] = s_f[FLEN + t];
        }

        // Per-sample ortho loss (thread 0)
        if (t == 0) {
            float lo[FLEN], hi[FLEN];
            float nl = 0.0f, nh = 0.0f;
#pragma unroll
            for (int f = 0; f < FLEN; ++f) {
                lo[f] = s_f[f];
                hi[f] = s_f[FLEN + f];
                nl = fmaf(lo[f], lo[f], nl);
                nh = fmaf(hi[f], hi[f], nh);
            }
            const float inl = rsqrtf(nl);
            const float inh = rsqrtf(nh);
            float Ln[FLEN], Hn[FLEN];
#pragma unroll
            for (int f = 0; f < FLEN; ++f) { Ln[f] = lo[f] * inl; Hn[f] = hi[f] * inh; }

            float ps = 0.0f;
            // shifts s = 1,3,5,7 ; rolled[i] = Ln[(i - s) mod 8]
#pragma unroll
            for (int s = 1; s < FLEN; s += 2) {
                float dot = 0.0f;
#pragma unroll
                for (int f = 0; f < FLEN; ++f)
                    dot = fmaf(Ln[f], Ln[(f - s) & (FLEN - 1)], dot);
                ps += fabsf(dot);
            }
            float dLH = 0.0f, dLL = 0.0f, dHH = 0.0f;
#pragma unroll
            for (int f = 0; f < FLEN; ++f) {
                dLH = fmaf(Ln[f], Hn[f], dLH);
                dLL = fmaf(Ln[f], Ln[f], dLL);
                dHH = fmaf(Hn[f], Hn[f], dHH);
            }
            ps += fabsf(dLH) + fabsf(dLL - 1.0f) + fabsf(dHH - 1.0f);
            g_loss[b] = ps;
        }
    }
}

// ---------------------------------------------------------------------------
// Reduce per-sample loss -> out[4096] (deterministic)
// ---------------------------------------------------------------------------
__global__ void __launch_bounds__(256) loss_reduce_kernel(float* __restrict__ out) {
    __shared__ float s[8];
    const int t = threadIdx.x;
    float v = g_loss[t];
#pragma unroll
    for (int off = 16; off; off >>= 1)
        v += __shfl_xor_sync(0xffffffffu, v, off);
    if ((t & 31) == 0) s[t >> 5] = v;
    __syncthreads();
    if (t < 8) {
        float w = s[t];
#pragma unroll
        for (int off = 4; off; off >>= 1)
            w += __shfl_xor_sync(0xffu, w, off);
        if (t == 0) out[2 * BATCH * FLEN] = w / (float)BATCH;
    }
}

// ---------------------------------------------------------------------------
extern "C" void kernel_launch(void* const* d_in, const int* in_sizes, int n_in,
                              void* d_out, int out_size) {
    const float* x  = (const float*)d_in[0];
    const float* W1 = (const float*)d_in[1];
    const float* b1 = (const float*)d_in[2];
    const float* W2 = (const float*)d_in[3];
    const float* b2 = (const float*)d_in[4];
    const float* W3 = (const float*)d_in[5];
    const float* b3 = (const float*)d_in[6];
    float* out = (float*)d_out;

    fused_kernel<<<BATCH, 1024>>>(x, W1, b1, W2, b2, W3, b3, out);
    loss_reduce_kernel<<<1, 256>>>(out);
}

// round 5
// speedup vs baseline: 1.1134x; 1.1134x over previous
#include <cuda_runtime.h>

#define BATCH 256
#define CHAN  512
#define SEQL  2048
#define HID   32
#define FLEN  8

// Scratch (no allocations allowed in kernel_launch)
__device__ float g_stat[BATCH * CHAN];

// ---------------------------------------------------------------------------
// Kernel 1: stat[b,c] = max over L of x[b,c,:]
// One warp per row. 2048 floats/row = 512 float4 = 16 float4 per lane.
// Streaming loads (__ldcs): x is touched exactly once.
// Block 0 / thread 0 zero-inits the loss accumulator out[4096].
// ---------------------------------------------------------------------------
__global__ void __launch_bounds__(256) max_rows_kernel(const float* __restrict__ x,
                                                       float* __restrict__ out) {
    if (blockIdx.x == 0 && threadIdx.x == 0)
        out[2 * BATCH * FLEN] = 0.0f;

    const int warp = (blockIdx.x * blockDim.x + threadIdx.x) >> 5;
    const int lane = threadIdx.x & 31;

    const float4* row = reinterpret_cast<const float4*>(x) + (size_t)warp * (SEQL / 4);

    float m = -3.402823466e38f;
#pragma unroll
    for (int i = 0; i < (SEQL / 4) / 32; ++i) {
        float4 v = __ldcs(row + i * 32 + lane);
        m = fmaxf(m, fmaxf(fmaxf(v.x, v.y), fmaxf(v.z, v.w)));
    }
#pragma unroll
    for (int off = 16; off; off >>= 1)
        m = fmaxf(m, __shfl_xor_sync(0xffffffffu, m, off));

    if (lane == 0) g_stat[warp] = m;
}

// ---------------------------------------------------------------------------
// Kernel 2: per-sample MLP + filters + ortho loss (atomicAdd to out[4096]).
// One block (256 threads = 8 warps) per batch sample.
// Warp w computes h1 units [4w, 4w+4) via coalesced warp-cooperative dots
// (serial depth 4 instead of 32).
// ---------------------------------------------------------------------------
__global__ void __launch_bounds__(256) mlp_kernel(
    const float* __restrict__ W1, const float* __restrict__ b1,
    const float* __restrict__ W2, const float* __restrict__ b2,
    const float* __restrict__ W3, const float* __restrict__ b3,
    float* __restrict__ out)
{
    __shared__ float4 s_stat4[CHAN / 4];
    __shared__ float  s_h1[HID];
    __shared__ float  s_h2[HID];
    __shared__ float  s_f[2 * FLEN];

    const int b    = blockIdx.x;
    const int tid  = threadIdx.x;
    const int warp = tid >> 5;   // 0..7
    const int lane = tid & 31;

    // Load stat row into smem (coalesced float4): 128 float4 over 256 threads
    const float4* srow = reinterpret_cast<const float4*>(g_stat + b * CHAN);
    if (tid < CHAN / 4)
        s_stat4[tid] = srow[tid];
    __syncthreads();

    // h1[h] = relu(dot(stat, W1[h,:]) + b1[h]); warp w owns h = 4w..4w+3.
    // The 4 dots are independent -> their LDGs and shuffle chains interleave.
    {
        float p[4];
#pragma unroll
        for (int j = 0; j < 4; ++j) {
            const int h = warp * 4 + j;
            const float4* w4 = reinterpret_cast<const float4*>(W1 + h * CHAN);
            float acc = 0.0f;
#pragma unroll
            for (int i = 0; i < 4; ++i) {
                float4 wv = __ldg(w4 + i * 32 + lane);
                float4 sv = s_stat4[i * 32 + lane];
                acc = fmaf(wv.x, sv.x, acc);
                acc = fmaf(wv.y, sv.y, acc);
                acc = fmaf(wv.z, sv.z, acc);
                acc = fmaf(wv.w, sv.w, acc);
            }
            p[j] = acc;
        }
#pragma unroll
        for (int off = 16; off; off >>= 1) {
#pragma unroll
            for (int j = 0; j < 4; ++j)
                p[j] += __shfl_xor_sync(0xffffffffu, p[j], off);
        }
        if (lane < 4) {
            const int h = warp * 4 + lane;
            // lane j holds p[j] only in registers of every lane; pick via shfl-free path:
            // all lanes have all four sums (butterfly), so lane j writes unit 4w+j.
            s_h1[h] = fmaxf(p[lane] + b1[h], 0.0f);
        }
    }
    __syncthreads();

    // ---- tiny layers + loss on warp 0 -------------------------------------
    if (warp == 0) {
        const int t = lane;

        // h2 = relu(h1 @ W2^T + b2): thread t owns unit t
        {
            float acc = b2[t];
            const float* w = W2 + t * HID;
#pragma unroll
            for (int k = 0; k < HID; ++k)
                acc = fmaf(s_h1[k], __ldg(w + k), acc);
            s_h2[t] = fmaxf(acc, 0.0f);
        }
        __syncwarp();

        // filters = h2 @ W3^T + b3 (16 outputs)
        if (t < 2 * FLEN) {
            float acc = b3[t];
            const float* w = W3 + t * HID;
#pragma unroll
            for (int k = 0; k < HID; ++k)
                acc = fmaf(s_h2[k], __ldg(w + k), acc);
            s_f[t] = acc;
        }
        __syncwarp();

        // Outputs: out[0:2048] = lo, out[2048:4096] = hi
        if (t < FLEN) {
            out[b * FLEN + t]                = s_f[t];
            out[BATCH * FLEN + b * FLEN + t] = s_f[FLEN + t];
        }

        // Per-sample ortho loss (thread 0), accumulated via atomicAdd (REDG)
        if (t == 0) {
            float lo[FLEN], hi[FLEN];
            float nl = 0.0f, nh = 0.0f;
#pragma unroll
            for (int f = 0; f < FLEN; ++f) {
                lo[f] = s_f[f];
                hi[f] = s_f[FLEN + f];
                nl = fmaf(lo[f], lo[f], nl);
                nh = fmaf(hi[f], hi[f], nh);
            }
            const float inl = rsqrtf(nl);
            const float inh = rsqrtf(nh);
            float Ln[FLEN], Hn[FLEN];
#pragma unroll
            for (int f = 0; f < FLEN; ++f) { Ln[f] = lo[f] * inl; Hn[f] = hi[f] * inh; }

            float ps = 0.0f;
            // shifts s = 1,3,5,7 ; rolled[i] = Ln[(i - s) mod 8]
#pragma unroll
            for (int s = 1; s < FLEN; s += 2) {
                float dot = 0.0f;
#pragma unroll
                for (int f = 0; f < FLEN; ++f)
                    dot = fmaf(Ln[f], Ln[(f - s) & (FLEN - 1)], dot);
                ps += fabsf(dot);
            }
            float dLH = 0.0f, dLL = 0.0f, dHH = 0.0f;
#pragma unroll
            for (int f = 0; f < FLEN; ++f) {
                dLH = fmaf(Ln[f], Hn[f], dLH);
                dLL = fmaf(Ln[f], Ln[f], dLL);
                dHH = fmaf(Hn[f], Hn[f], dHH);
            }
            ps += fabsf(dLH) + fabsf(dLL - 1.0f) + fabsf(dHH - 1.0f);
            atomicAdd(out + 2 * BATCH * FLEN, ps * (1.0f / (float)BATCH));
        }
    }
}

// ---------------------------------------------------------------------------
extern "C" void kernel_launch(void* const* d_in, const int* in_sizes, int n_in,
                              void* d_out, int out_size) {
    const float* x  = (const float*)d_in[0];
    const float* W1 = (const float*)d_in[1];
    const float* b1 = (const float*)d_in[2];
    const float* W2 = (const float*)d_in[3];
    const float* b2 = (const float*)d_in[4];
    const float* W3 = (const float*)d_in[5];
    const float* b3 = (const float*)d_in[6];
    float* out = (float*)d_out;

    // Kernel 1: 256*512 = 131072 rows, 8 warps/block -> 16384 blocks
    max_rows_kernel<<<(BATCH * CHAN) / 8, 256>>>(x, out);
    // Kernel 2: one 256-thread block per sample (also accumulates the loss)
    mlp_kernel<<<BATCH, 256>>>(W1, b1, W2, b2, W3, b3, out);
}